// round 4
// baseline (speedup 1.0000x reference)
#include <cuda_runtime.h>
#include <cuda_bf16.h>
#include <cstdint>

#define MAXN 100000
#define MAXE 1600000
#define F 64

// -------- scratch (static device globals; no allocation allowed) ----------
__device__ float g_agg[(size_t)MAXN * F];
__device__ float g_h1[(size_t)MAXN * F];
__device__ int   g_deg[MAXN];
__device__ int   g_rowstart[MAXN];
__device__ int   g_cursor[MAXN];
__device__ int   g_eidx[MAXE];
__device__ int   g_is64;

// --------------------- edge dtype detection (int64 vs int32) ---------------
// Reference claims int64, but JAX without x64 silently emits int32. Detect on
// device: if the first 64 slots interpreted as int64 are all in [0, n), the
// buffer is int64 (random int32 pairs combine to >= 2^32 almost surely).
__global__ void k_detect(const void* __restrict__ eiv, int n) {
    if (threadIdx.x == 0 && blockIdx.x == 0) {
        const long long* p = (const long long*)eiv;
        int ok = 1;
        #pragma unroll 1
        for (int i = 0; i < 64; i++) {
            long long v = p[i];
            if (v < 0 || v >= (long long)n) { ok = 0; break; }
        }
        g_is64 = ok;
    }
}

__device__ __forceinline__ int load_edge(const void* eiv, size_t idx, int n) {
    int v;
    if (g_is64) v = (int)((const long long*)eiv)[idx];
    else        v = ((const int*)eiv)[idx];
    // clamp: wrong detection degrades accuracy (visible), never traps
    return min(max(v, 0), n - 1);
}

// --------------------------- CSR build ------------------------------------
__global__ void k_zero_deg(int n) {
    int i = blockIdx.x * blockDim.x + threadIdx.x;
    if (i < n) g_deg[i] = 0;
}

__global__ void k_count(const void* __restrict__ eiv, int E, int n) {
    int e = blockIdx.x * blockDim.x + threadIdx.x;
    if (e < E) {
        int d = load_edge(eiv, (size_t)E + e, n);
        atomicAdd(&g_deg[d], 1);
    }
}

// single-block exclusive scan: deg -> rowstart, cursor. 1024 threads.
__global__ void k_scan(int n) {
    __shared__ int sh[1024];
    __shared__ int carry;
    int tid = threadIdx.x;
    if (tid == 0) carry = 0;
    __syncthreads();
    for (int base = 0; base < n; base += 4096) {
        int idx0 = base + tid * 4;
        int v[4];
        #pragma unroll
        for (int i = 0; i < 4; i++) {
            int id = idx0 + i;
            int idc = id < n ? id : (n - 1);
            int val = g_deg[idc];
            v[i] = (id < n) ? val : 0;
        }
        int tot = v[0] + v[1] + v[2] + v[3];
        sh[tid] = tot;
        __syncthreads();
        #pragma unroll
        for (int off = 1; off < 1024; off <<= 1) {
            int src = (tid >= off) ? (tid - off) : tid;
            int t = sh[src];
            if (tid < off) t = 0;
            __syncthreads();
            sh[tid] += t;
            __syncthreads();
        }
        int run = carry + sh[tid] - tot;
        #pragma unroll
        for (int i = 0; i < 4; i++) {
            int id = idx0 + i;
            if (id < n) { g_rowstart[id] = run; g_cursor[id] = run; }
            run += v[i];
        }
        __syncthreads();
        if (tid == 0) carry += sh[1023];
        __syncthreads();
    }
}

__global__ void k_fill(const void* __restrict__ eiv, int E, int n) {
    int e = blockIdx.x * blockDim.x + threadIdx.x;
    if (e < E) {
        int d = load_edge(eiv, (size_t)E + e, n);
        int s = load_edge(eiv, (size_t)e, n);
        int pos = atomicAdd(&g_cursor[d], 1);
        if (pos < MAXE) g_eidx[pos] = s;
    }
}

// ------------------------ mean aggregation (gather-side) -------------------
// one warp per node; each lane owns one float2 (features 2*lane, 2*lane+1)
__device__ __forceinline__ void agg_body(const float* __restrict__ feat, int n) {
    int w = (blockIdx.x * blockDim.x + threadIdx.x) >> 5;
    int lane = threadIdx.x & 31;
    if (w >= n) return;
    int s = g_rowstart[w];
    int d = g_deg[w];
    float2 acc = make_float2(0.f, 0.f);
    const float2* f2 = (const float2*)feat;
    int i = 0;
    for (; i + 1 < d; i += 2) {
        int s0 = g_eidx[s + i];
        int s1 = g_eidx[s + i + 1];
        float2 a = f2[(size_t)s0 * 32 + lane];
        float2 b = f2[(size_t)s1 * 32 + lane];
        acc.x += a.x + b.x;
        acc.y += a.y + b.y;
    }
    if (i < d) {
        int s0 = g_eidx[s + i];
        float2 a = f2[(size_t)s0 * 32 + lane];
        acc.x += a.x; acc.y += a.y;
    }
    float inv = 1.0f / (float)max(d, 1);
    acc.x *= inv; acc.y *= inv;
    ((float2*)g_agg)[(size_t)w * 32 + lane] = acc;
}

__global__ void k_agg_x(const float* __restrict__ x, int n)  { agg_body(x, n); }
__global__ void k_agg_h1(int n)                              { agg_body(g_h1, n); }

// ------------------------ fused dual-GEMM + bias + ReLU --------------------
// 64-row tile per block, 256 threads, 4x4 microtile per thread.
__global__ void k_gemm_relu(const float* __restrict__ A0, const float* __restrict__ W0,
                            const float* __restrict__ W1,
                            const float* __restrict__ bias, int n)
{
    __shared__ __align__(16) float As[64][68];   // [k][row]
    __shared__ __align__(16) float Ws[64][64];   // [k][col]
    int tid = threadIdx.x;
    int row0 = blockIdx.x * 64;
    int tx = tid & 15, ty = tid >> 4;
    int r0 = ty * 4, c0 = tx * 4;
    float acc[4][4] = {};

    #pragma unroll
    for (int pass = 0; pass < 2; pass++) {
        const float* A = pass ? (const float*)g_agg : A0;
        const float* W = pass ? W1 : W0;
        __syncthreads();
        {
            int r  = tid >> 2;
            int kc = (tid & 3) * 16;
            int gr = row0 + r;
            int grc = gr < n ? gr : (n - 1);   // clamp: always-valid address
            const float4* a4 = (const float4*)(A + (size_t)grc * 64 + kc);
            #pragma unroll
            for (int i = 0; i < 4; i++) {
                float4 v = a4[i];
                int k = kc + i * 4;
                As[k + 0][r] = v.x; As[k + 1][r] = v.y;
                As[k + 2][r] = v.z; As[k + 3][r] = v.w;
            }
            int kk = tid >> 2;
            int jc = (tid & 3) * 16;
            const float4* w4 = (const float4*)(W + kk * 64 + jc);
            float4* ws4 = (float4*)(&Ws[kk][jc]);
            #pragma unroll
            for (int i = 0; i < 4; i++) ws4[i] = w4[i];
        }
        __syncthreads();
        #pragma unroll 8
        for (int k = 0; k < 64; k++) {
            float4 av = *(const float4*)(&As[k][r0]);
            float4 wv = *(const float4*)(&Ws[k][c0]);
            float a[4] = {av.x, av.y, av.z, av.w};
            float w[4] = {wv.x, wv.y, wv.z, wv.w};
            #pragma unroll
            for (int i = 0; i < 4; i++)
                #pragma unroll
                for (int j = 0; j < 4; j++)
                    acc[i][j] += a[i] * w[j];
        }
    }
    float4 bv = *(const float4*)(bias + c0);
    float bb[4] = {bv.x, bv.y, bv.z, bv.w};
    #pragma unroll
    for (int i = 0; i < 4; i++) {
        int gr = row0 + r0 + i;
        if (gr < n) {
            float4 o;
            o.x = fmaxf(acc[i][0] + bb[0], 0.f);
            o.y = fmaxf(acc[i][1] + bb[1], 0.f);
            o.z = fmaxf(acc[i][2] + bb[2], 0.f);
            o.w = fmaxf(acc[i][3] + bb[3], 0.f);
            *(float4*)(g_h1 + (size_t)gr * 64 + c0) = o;
        }
    }
}

// layer-2 variant: A0 = g_h1, A1 = g_agg; h2 stays in shared; fused 64->2 head.
__global__ void k_gemm_relu_final(const float* __restrict__ W0,
                                  const float* __restrict__ W1,
                                  const float* __restrict__ bias,
                                  const float* __restrict__ Wlin, const float* __restrict__ blin,
                                  float* __restrict__ out, int n)
{
    __shared__ __align__(16) float As[64][68];   // [k][row]; reused as Hs[c][row]
    __shared__ __align__(16) float Ws[64][64];
    __shared__ float Wls[128];
    __shared__ float bls[2];
    int tid = threadIdx.x;
    int row0 = blockIdx.x * 64;
    int tx = tid & 15, ty = tid >> 4;
    int r0 = ty * 4, c0 = tx * 4;
    float acc[4][4] = {};

    if (tid < 128) Wls[tid] = Wlin[tid];
    if (tid < 2)   bls[tid] = blin[tid];

    #pragma unroll
    for (int pass = 0; pass < 2; pass++) {
        const float* A = pass ? (const float*)g_agg : (const float*)g_h1;
        const float* W = pass ? W1 : W0;
        __syncthreads();
        {
            int r  = tid >> 2;
            int kc = (tid & 3) * 16;
            int gr = row0 + r;
            int grc = gr < n ? gr : (n - 1);
            const float4* a4 = (const float4*)(A + (size_t)grc * 64 + kc);
            #pragma unroll
            for (int i = 0; i < 4; i++) {
                float4 v = a4[i];
                int k = kc + i * 4;
                As[k + 0][r] = v.x; As[k + 1][r] = v.y;
                As[k + 2][r] = v.z; As[k + 3][r] = v.w;
            }
            int kk = tid >> 2;
            int jc = (tid & 3) * 16;
            const float4* w4 = (const float4*)(W + kk * 64 + jc);
            float4* ws4 = (float4*)(&Ws[kk][jc]);
            #pragma unroll
            for (int i = 0; i < 4; i++) ws4[i] = w4[i];
        }
        __syncthreads();
        #pragma unroll 8
        for (int k = 0; k < 64; k++) {
            float4 av = *(const float4*)(&As[k][r0]);
            float4 wv = *(const float4*)(&Ws[k][c0]);
            float a[4] = {av.x, av.y, av.z, av.w};
            float w[4] = {wv.x, wv.y, wv.z, wv.w};
            #pragma unroll
            for (int i = 0; i < 4; i++)
                #pragma unroll
                for (int j = 0; j < 4; j++)
                    acc[i][j] += a[i] * w[j];
        }
    }
    float4 bv = *(const float4*)(bias + c0);
    float bb[4] = {bv.x, bv.y, bv.z, bv.w};
    __syncthreads();
    #pragma unroll
    for (int i = 0; i < 4; i++)
        #pragma unroll
        for (int j = 0; j < 4; j++)
            As[c0 + j][r0 + i] = fmaxf(acc[i][j] + bb[j], 0.f);
    __syncthreads();
    if (tid < 128) {
        int r = tid >> 1, j = tid & 1;
        int gr = row0 + r;
        if (gr < n) {
            float s = bls[j];
            #pragma unroll 8
            for (int c = 0; c < 64; c++)
                s += As[c][r] * Wls[c * 2 + j];
            out[(size_t)gr * 2 + j] = s;
        }
    }
}

// ------------------------------ launch -------------------------------------
extern "C" void kernel_launch(void* const* d_in, const int* in_sizes, int n_in,
                              void* d_out, int out_size)
{
    const float* x      = (const float*)d_in[0];
    const void*  ei     = d_in[1];                 // int64 OR int32, detected on device
    const float* W1_agg = (const float*)d_in[2];
    const float* W1_root= (const float*)d_in[3];
    const float* b1     = (const float*)d_in[4];
    const float* W2_agg = (const float*)d_in[5];
    const float* W2_root= (const float*)d_in[6];
    const float* b2     = (const float*)d_in[7];
    const float* W_lin  = (const float*)d_in[8];
    const float* b_lin  = (const float*)d_in[9];
    float*       out    = (float*)d_out;

    int n = in_sizes[0] / F;       // 100000
    int E = in_sizes[1] / 2;       // 1600000

    // CSR build (reused by both layers)
    k_detect<<<1, 32>>>(ei, n);
    k_zero_deg<<<(n + 255) / 256, 256>>>(n);
    k_count<<<(E + 255) / 256, 256>>>(ei, E, n);
    k_scan<<<1, 1024>>>(n);
    k_fill<<<(E + 255) / 256, 256>>>(ei, E, n);

    int agg_blocks = (n * 32 + 255) / 256;
    int gemm_blocks = (n + 63) / 64;

    // layer 1: agg(x) -> g_agg; h1 = relu(x@W1_root + agg@W1_agg + b1) -> g_h1
    k_agg_x<<<agg_blocks, 256>>>(x, n);
    k_gemm_relu<<<gemm_blocks, 256>>>(x, W1_root, W1_agg, b1, n);
    // layer 2 + fused output head
    k_agg_h1<<<agg_blocks, 256>>>(n);
    k_gemm_relu_final<<<gemm_blocks, 256>>>(W2_root, W2_agg, b2, W_lin, b_lin, out, n);
}